// round 1
// baseline (speedup 1.0000x reference)
#include <cuda_runtime.h>

#define BATCH  4096
#define TSTEPS 100
#define DDIM   100
#define OOUT   3

// One warp per batch element. Lanes 0..24 each own a float4 chunk of the
// 100-element row; per timestep: load x/u chunk, spikes = (u<x), predicated
// accumulate against 3 register-resident W rows, butterfly-reduce, update
// the 3-element leaky membrane state (redundantly on all lanes), lane 0
// writes spk/mem.
__global__ __launch_bounds__(256) void leaky_kernel(
    const float* __restrict__ x, const float* __restrict__ u,
    const float* __restrict__ W, const float* __restrict__ bias,
    const float* __restrict__ betap, const float* __restrict__ thrp,
    float* __restrict__ out)
{
    const int gw   = (blockIdx.x * blockDim.x + threadIdx.x) >> 5;
    const int lane = threadIdx.x & 31;
    if (gw >= BATCH) return;

    const float beta = __ldg(betap);
    const float thr  = __ldg(thrp);
    const float bb0 = __ldg(bias + 0);
    const float bb1 = __ldg(bias + 1);
    const float bb2 = __ldg(bias + 2);

    const bool act = (lane < (DDIM / 4));  // 25 active load lanes
    float4 w0 = make_float4(0.f, 0.f, 0.f, 0.f), w1 = w0, w2 = w0;
    if (act) {
        // W rows are 100 floats = 400 B each -> every row start is 16B aligned.
        w0 = *(const float4*)(W + 0 * DDIM + 4 * lane);
        w1 = *(const float4*)(W + 1 * DDIM + 4 * lane);
        w2 = *(const float4*)(W + 2 * DDIM + 4 * lane);
    }

    const float4* xb = (const float4*)(x + (size_t)gw * (TSTEPS * DDIM));
    const float4* ub = (const float4*)(u + (size_t)gw * (TSTEPS * DDIM));

    float m0 = 0.f, m1 = 0.f, m2 = 0.f;
    float* __restrict__ spk = out;
    float* __restrict__ mem = out + (size_t)TSTEPS * BATCH * OOUT;

    // Prefetch row 0
    float4 xv = make_float4(0.f, 0.f, 0.f, 0.f), uv = xv;
    if (act) { xv = __ldg(xb + lane); uv = __ldg(ub + lane); }

    #pragma unroll 2
    for (int t = 0; t < TSTEPS; ++t) {
        // Prefetch row t+1 (independent of the mem recurrence -> MLP=2)
        float4 xn = make_float4(0.f, 0.f, 0.f, 0.f), un = xn;
        if (act && (t + 1 < TSTEPS)) {
            xn = __ldg(xb + (t + 1) * (DDIM / 4) + lane);
            un = __ldg(ub + (t + 1) * (DDIM / 4) + lane);
        }

        float p0 = 0.f, p1 = 0.f, p2 = 0.f;
        if (act) {
            if (uv.x < xv.x) { p0 += w0.x; p1 += w1.x; p2 += w2.x; }
            if (uv.y < xv.y) { p0 += w0.y; p1 += w1.y; p2 += w2.y; }
            if (uv.z < xv.z) { p0 += w0.z; p1 += w1.z; p2 += w2.z; }
            if (uv.w < xv.w) { p0 += w0.w; p1 += w1.w; p2 += w2.w; }
        }
        #pragma unroll
        for (int off = 16; off; off >>= 1) {
            p0 += __shfl_xor_sync(0xffffffffu, p0, off);
            p1 += __shfl_xor_sync(0xffffffffu, p1, off);
            p2 += __shfl_xor_sync(0xffffffffu, p2, off);
        }

        const float c0 = p0 + bb0;
        const float c1 = p1 + bb1;
        const float c2 = p2 + bb2;

        // reset from PREVIOUS mem: heaviside(mem - thr) * thr
        const float r0 = (m0 - thr > 0.f) ? thr : 0.f;
        const float r1 = (m1 - thr > 0.f) ? thr : 0.f;
        const float r2 = (m2 - thr > 0.f) ? thr : 0.f;
        m0 = beta * m0 + c0 - r0;
        m1 = beta * m1 + c1 - r1;
        m2 = beta * m2 + c2 - r2;

        if (lane == 0) {
            const size_t o = (size_t)t * (BATCH * OOUT) + (size_t)gw * OOUT;
            spk[o + 0] = (m0 - thr > 0.f) ? 1.f : 0.f;
            spk[o + 1] = (m1 - thr > 0.f) ? 1.f : 0.f;
            spk[o + 2] = (m2 - thr > 0.f) ? 1.f : 0.f;
            mem[o + 0] = m0;
            mem[o + 1] = m1;
            mem[o + 2] = m2;
        }

        xv = xn; uv = un;
    }
}

extern "C" void kernel_launch(void* const* d_in, const int* in_sizes, int n_in,
                              void* d_out, int out_size)
{
    const float* x    = (const float*)d_in[0];
    const float* u    = (const float*)d_in[1];
    const float* W    = (const float*)d_in[2];
    const float* bias = (const float*)d_in[3];
    const float* beta = (const float*)d_in[4];
    const float* thr  = (const float*)d_in[5];
    float* out = (float*)d_out;

    const int threads = 256;                       // 8 warps/block
    const int blocks  = (BATCH * 32) / threads;    // 512 blocks
    leaky_kernel<<<blocks, threads>>>(x, u, W, bias, beta, thr, out);
}